// round 11
// baseline (speedup 1.0000x reference)
#include <cuda_runtime.h>
#include <cuda_bf16.h>
#include <cuda_fp16.h>
#include <math.h>
#include <stdint.h>

#define BB 4
#define SS 1024
#define DD 1024
#define HH 16
#define HD 64

typedef unsigned short ushort_t;

#define NACT (BB*SS*DD)           // 4M elements per activation plane

__device__ __half   g_Pf[(size_t)BB*HH*SS*SS];    // unnormalized exp scores fp16 (128MB)
__device__ float    g_Sp[BB*HH*SS*16];            // per-row partial sums (4MB)
__device__ float    g_invS[BB*HH*SS];             // 1/rowsum (256KB)
__device__ __half   g_Qf[BB*HH*SS*HD];
__device__ __half   g_Kf[BB*HH*SS*HD];
__device__ __half   g_Vf[BB*HH*SS*HD];
__device__ ushort_t g_Xhi[NACT], g_Xlo[NACT];     // X fp16 hi/lo planes
__device__ ushort_t g_Ahi[3*NACT], g_Alo[3*NACT]; // q/k/v activation fp16 hi/lo
__device__ ushort_t g_Bf [4*DD*DD];               // W^T fp16: q,k,v,o planes

// ---------------- helpers ----------------
__device__ __forceinline__ uint32_t smem_to_u32(const void* p) {
    uint32_t a;
    asm("{ .reg .u64 t; cvta.to.shared.u64 t, %1; cvt.u32.u64 %0, t; }"
        : "=r"(a) : "l"(p));
    return a;
}
__device__ __forceinline__ void cpa16(uint32_t s, const void* g) {
    asm volatile("cp.async.cg.shared.global [%0], [%1], 16;" :: "r"(s), "l"(g));
}
#define CP_COMMIT() asm volatile("cp.async.commit_group;")
#define CP_WAIT(n)  asm volatile("cp.async.wait_group %0;" :: "n"(n))

__device__ __forceinline__ void ldsm4(uint32_t* r, uint32_t addr) {
    asm volatile("ldmatrix.sync.aligned.m8n8.x4.shared.b16 {%0,%1,%2,%3}, [%4];"
        : "=r"(r[0]), "=r"(r[1]), "=r"(r[2]), "=r"(r[3]) : "r"(addr));
}
__device__ __forceinline__ void ldsm4t(uint32_t* r, uint32_t addr) {
    asm volatile("ldmatrix.sync.aligned.m8n8.x4.trans.shared.b16 {%0,%1,%2,%3}, [%4];"
        : "=r"(r[0]), "=r"(r[1]), "=r"(r[2]), "=r"(r[3]) : "r"(addr));
}
__device__ __forceinline__ void mma16816h(float* c, const uint32_t* a,
                                          uint32_t b0, uint32_t b1) {
    asm volatile(
        "mma.sync.aligned.m16n8k16.row.col.f32.f16.f16.f32 "
        "{%0,%1,%2,%3}, {%4,%5,%6,%7}, {%8,%9}, {%0,%1,%2,%3};"
        : "+f"(c[0]), "+f"(c[1]), "+f"(c[2]), "+f"(c[3])
        : "r"(a[0]), "r"(a[1]), "r"(a[2]), "r"(a[3]), "r"(b0), "r"(b1));
}
__device__ __forceinline__ void split1h(float v, ushort_t& h, ushort_t& l) {
    __half hb = __float2half_rn(v);
    float r = v - __half2float(hb);
    __half lb = __float2half_rn(r);
    h = __half_as_ushort(hb);
    l = __half_as_ushort(lb);
}

// ---------------- splits (merged launches) ----------------
__global__ __launch_bounds__(256) void split_act3(
    const float4* __restrict__ x0, const float4* __restrict__ x1,
    const float4* __restrict__ x2)
{
    const int z = blockIdx.y;
    const float4* x = (z == 0) ? x0 : (z == 1) ? x1 : x2;
    uint2* hi = reinterpret_cast<uint2*>(g_Ahi) + (size_t)z * (NACT/4);
    uint2* lo = reinterpret_cast<uint2*>(g_Alo) + (size_t)z * (NACT/4);
    int i = blockIdx.x * blockDim.x + threadIdx.x;
    float4 v = x[i];
    ushort_t h0,h1,h2,h3,l0,l1,l2,l3;
    split1h(v.x,h0,l0); split1h(v.y,h1,l1); split1h(v.z,h2,l2); split1h(v.w,h3,l3);
    hi[i] = make_uint2((uint32_t)h0 | ((uint32_t)h1 << 16),
                       (uint32_t)h2 | ((uint32_t)h3 << 16));
    lo[i] = make_uint2((uint32_t)l0 | ((uint32_t)l1 << 16),
                       (uint32_t)l2 | ((uint32_t)l3 << 16));
}

__global__ __launch_bounds__(256) void split_wT4(
    const float* __restrict__ W0, const float* __restrict__ W1,
    const float* __restrict__ W2, const float* __restrict__ W3)
{
    const int z = blockIdx.z;
    const float* W = (z == 0) ? W0 : (z == 1) ? W1 : (z == 2) ? W2 : W3;
    ushort_t* bf = g_Bf + (size_t)z * DD * DD;
    __shared__ float t[32][33];
    int n0 = blockIdx.x * 32, k0 = blockIdx.y * 32;
    int tx = threadIdx.x & 31, ty = threadIdx.x >> 5;
    #pragma unroll
    for (int j = 0; j < 4; j++)
        t[ty + 8*j][tx] = W[(size_t)(k0 + ty + 8*j) * DD + n0 + tx];
    __syncthreads();
    #pragma unroll
    for (int j = 0; j < 4; j++) {
        float v = t[tx][ty + 8*j];
        bf[(size_t)(n0 + ty + 8*j) * DD + k0 + tx]
            = __half_as_ushort(__float2half_rn(v));
    }
}

// ---------------- projection GEMM (fp16 split-2) ----------------
#define PJ_TILE  10240
#define PJ_STAGE (3*PJ_TILE)
#define PJ_SMEM  (2*PJ_STAGE)

__device__ __forceinline__ void proj_core(
    const ushort_t* __restrict__ Ahi, const ushort_t* __restrict__ Alo,
    const ushort_t* __restrict__ Bf, const float* __restrict__ bias,
    __half* __restrict__ Cf, float* __restrict__ Cext,
    char* smem, int m0, int n0)
{
    const uint32_t sb = smem_to_u32(smem);
    const int tid = threadIdx.x, lane = tid & 31, wid = tid >> 5;
    const int wm = wid >> 1, wn = wid & 1;

    const ushort_t* gsrc[3] = {Ahi, Alo, Bf};

    auto issue = [&](int stage, int k0) {
        #pragma unroll
        for (int i = 0; i < 6; i++) {
            int cid = i * 256 + tid;
            int t = cid >> 9;
            int idx = cid & 511;
            int r = idx >> 2, c = idx & 3;
            int grow = (t < 2 ? m0 : n0) + r;
            const ushort_t* g = gsrc[t] + (size_t)grow * 1024 + k0 + c * 8;
            cpa16(sb + stage * PJ_STAGE + t * PJ_TILE + r * 80 + c * 16, g);
        }
        CP_COMMIT();
    };

    float acc[2][8][4];
    #pragma unroll
    for (int i = 0; i < 2; i++)
        #pragma unroll
        for (int j = 0; j < 8; j++)
            #pragma unroll
            for (int c = 0; c < 4; c++) acc[i][j][c] = 0.f;

    issue(0, 0);
    for (int kc = 0; kc < 32; kc++) {
        if (kc < 31) { issue((kc + 1) & 1, (kc + 1) * 32); CP_WAIT(1); }
        else CP_WAIT(0);
        __syncthreads();
        const uint32_t s0  = sb + (kc & 1) * PJ_STAGE;
        const uint32_t sAh = s0, sAl = s0 + PJ_TILE, sB = s0 + 2*PJ_TILE;

        #pragma unroll
        for (int ks = 0; ks < 2; ks++) {
            uint32_t ah[2][4], al[2][4];
            #pragma unroll
            for (int i = 0; i < 2; i++) {
                uint32_t off = (uint32_t)(wm*32 + i*16 + (lane & 15)) * 80
                             + ((lane >> 4) * 16) + ks * 32;
                ldsm4(ah[i], sAh + off);
                ldsm4(al[i], sAl + off);
            }
            uint32_t b4[4][4];
            #pragma unroll
            for (int j4 = 0; j4 < 4; j4++) {
                uint32_t row = (uint32_t)(wn*64 + j4*16 + (lane & 7) + ((lane & 16) >> 1));
                uint32_t off = row * 80 + ks * 32 + ((lane & 8) << 1);
                ldsm4(b4[j4], sB + off);
            }
            #pragma unroll
            for (int i = 0; i < 2; i++)
                #pragma unroll
                for (int j = 0; j < 8; j++) {
                    int j4 = j >> 1, hh = (j & 1) * 2;
                    mma16816h(acc[i][j], ah[i], b4[j4][hh], b4[j4][hh+1]);
                    mma16816h(acc[i][j], al[i], b4[j4][hh], b4[j4][hh+1]);
                }
        }
        __syncthreads();
    }

    #pragma unroll
    for (int i = 0; i < 2; i++) {
        int mlo = m0 + wm*32 + i*16 + (lane >> 2);
        #pragma unroll
        for (int half = 0; half < 2; half++) {
            int m = mlo + half * 8;
            int b = m >> 10, s = m & 1023;
            #pragma unroll
            for (int j = 0; j < 8; j++) {
                int col = n0 + wn*64 + j*8 + 2*(lane & 3);
                float v0 = acc[i][j][half*2 + 0] + bias[col];
                float v1 = acc[i][j][half*2 + 1] + bias[col + 1];
                if (Cext) {
                    *reinterpret_cast<float2*>(Cext + (size_t)m * 1024 + col)
                        = make_float2(v0, v1);
                } else {
                    int h = col >> 6, hd = col & 63;
                    size_t o = ((size_t)((b << 4) + h) * 1024 + s) * 64 + hd;
                    *reinterpret_cast<__half2*>(Cf + o) = __floats2half2_rn(v0, v1);
                }
            }
        }
    }
}

__global__ __launch_bounds__(256) void proj_qkv(
    const float* __restrict__ b0, const float* __restrict__ b1,
    const float* __restrict__ b2)
{
    extern __shared__ char smem[];
    const int z = blockIdx.z;
    const ushort_t* Ahi = g_Ahi + (size_t)z * NACT;
    const ushort_t* Alo = g_Alo + (size_t)z * NACT;
    const ushort_t* Bf  = g_Bf  + (size_t)z * DD * DD;
    const float* bias = (z == 0) ? b0 : (z == 1) ? b1 : b2;
    __half* Cf = (z == 0) ? g_Qf : (z == 1) ? g_Kf : g_Vf;
    proj_core(Ahi, Alo, Bf, bias, Cf, nullptr, smem,
              blockIdx.y * 128, blockIdx.x * 128);
}

__global__ __launch_bounds__(256) void proj_out(
    const float* __restrict__ bias, float* __restrict__ Cext)
{
    extern __shared__ char smem[];
    proj_core(g_Xhi, g_Xlo, g_Bf + (size_t)3 * DD * DD, bias, nullptr, Cext,
              smem, blockIdx.y * 128, blockIdx.x * 128);
}

// ---------------- scores + exp (unnormalized softmax) ----------------
// Per (bh, 128x128 tile): S = Q K^T; e = exp(S*0.125) written fp16 to g_Pf
// (staged via reused smem for coalescing); per-row partial sums -> g_Sp.
// No max subtraction: |s*0.125| <~ 6 sigma, e^6=403 << fp16 max.
#define SC_TILE  18432            // 128 rows * 72 elems * 2B
#define SC_SMEM  (2*SC_TILE)      // 36864 ; staging reuses [0, 128*272=34816)

__global__ __launch_bounds__(256) void scores_exp()
{
    extern __shared__ char smem[];
    const uint32_t sb = smem_to_u32(smem);
    const int tid = threadIdx.x, lane = tid & 31, wid = tid >> 5;
    const int wm = wid >> 1, wn = wid & 1;
    const int bh = blockIdx.z;
    const int m0 = blockIdx.y * 128, n0 = blockIdx.x * 128;
    const int ntile = blockIdx.x;

    #pragma unroll
    for (int i = 0; i < 8; i++) {
        int cid = i * 256 + tid;
        int t = cid >> 10;
        int idx = cid & 1023;
        int r = idx >> 3, c = idx & 7;
        int base = (t == 0 ? m0 : n0);
        const __half* g = (t == 0 ? g_Qf : g_Kf)
            + ((size_t)bh * 1024 + base + r) * 64 + c * 8;
        cpa16(sb + t * SC_TILE + r * 144 + c * 16, g);
    }
    CP_COMMIT();
    CP_WAIT(0);
    __syncthreads();

    const uint32_t sQ = sb, sK = sb + SC_TILE;

    float acc[2][8][4];
    #pragma unroll
    for (int i = 0; i < 2; i++)
        #pragma unroll
        for (int j = 0; j < 8; j++)
            #pragma unroll
            for (int c = 0; c < 4; c++) acc[i][j][c] = 0.f;

    #pragma unroll
    for (int ks = 0; ks < 4; ks++) {
        uint32_t a[2][4];
        #pragma unroll
        for (int i = 0; i < 2; i++) {
            uint32_t off = (uint32_t)(wm*32 + i*16 + (lane & 15)) * 144
                         + ((lane >> 4) * 16) + ks * 32;
            ldsm4(a[i], sQ + off);
        }
        uint32_t b4[4][4];
        #pragma unroll
        for (int j4 = 0; j4 < 4; j4++) {
            uint32_t row = (uint32_t)(wn*64 + j4*16 + (lane & 7) + ((lane & 16) >> 1));
            uint32_t off = row * 144 + ks * 32 + ((lane & 8) << 1);
            ldsm4(b4[j4], sK + off);
        }
        #pragma unroll
        for (int i = 0; i < 2; i++)
            #pragma unroll
            for (int j = 0; j < 8; j++) {
                int j4 = j >> 1, hh = (j & 1) * 2;
                mma16816h(acc[i][j], a[i], b4[j4][hh], b4[j4][hh+1]);
            }
    }

    __syncthreads();   // K/Q smem dead; reuse as fp16 staging (272B rows)

    // exp + per-row partial sums + stage to smem
    #pragma unroll
    for (int i = 0; i < 2; i++) {
        int rl0 = wm*32 + i*16 + (lane >> 2);   // local row
        #pragma unroll
        for (int half = 0; half < 2; half++) {
            int rl = rl0 + half * 8;
            float rsum = 0.f;
            #pragma unroll
            for (int j = 0; j < 8; j++) {
                int col = wn*64 + j*8 + 2*(lane & 3);
                float e0 = expf(acc[i][j][half*2 + 0] * 0.125f);
                float e1 = expf(acc[i][j][half*2 + 1] * 0.125f);
                rsum += e0 + e1;
                *reinterpret_cast<__half2*>(smem + rl*272 + col*2)
                    = __floats2half2_rn(e0, e1);
            }
            rsum += __shfl_xor_sync(0xffffffffu, rsum, 1);
            rsum += __shfl_xor_sync(0xffffffffu, rsum, 2);
            if ((lane & 3) == 0)
                g_Sp[((size_t)bh*1024 + m0 + rl)*16 + ntile*2 + wn] = rsum;
        }
    }
    __syncthreads();

    // coalesced copy-out: warp w handles rows w*16..w*16+15
    __half* Pp = g_Pf + (size_t)bh * SS * SS;
    #pragma unroll
    for (int rr = 0; rr < 16; rr++) {
        int row = wid * 16 + rr;
        uint2 v = *reinterpret_cast<uint2*>(smem + row*272 + lane*8);
        *reinterpret_cast<uint2*>(Pp + (size_t)(m0 + row) * SS + n0 + lane*4) = v;
    }
}

// ---------------- sumS: combine partials -> 1/S ----------------
__global__ __launch_bounds__(256) void sumS()
{
    int r = blockIdx.x * 256 + threadIdx.x;      // 0..65535
    const float4* p = reinterpret_cast<const float4*>(g_Sp + (size_t)r * 16);
    float4 a = p[0], b = p[1], c = p[2], d = p[3];
    float s = a.x+a.y+a.z+a.w + b.x+b.y+b.z+b.w
            + c.x+c.y+c.z+c.w + d.x+d.y+d.z+d.w;
    g_invS[r] = 1.f / s;
}

// ---------------- attn_c from unnormalized Pf ----------------
__global__ __launch_bounds__(256) void attnc(
    const float* __restrict__ Wc, const float* __restrict__ bcp,
    float* __restrict__ attn_out)
{
    const int b = blockIdx.x >> 10;
    const int q = blockIdx.x & 1023;
    const int t = threadIdx.x;

    float a0 = 0.f, a1 = 0.f, a2 = 0.f, a3 = 0.f;
    #pragma unroll
    for (int h = 0; h < HH; h++) {
        const size_t rowbase = (size_t)((b << 4) + h) * SS + q;
        const uint2 v = *reinterpret_cast<const uint2*>(
            g_Pf + rowbase * SS + t * 4);
        float2 p01 = __half22float2(*reinterpret_cast<const __half2*>(&v.x));
        float2 p23 = __half22float2(*reinterpret_cast<const __half2*>(&v.y));
        float w = Wc[h] * g_invS[rowbase];
        a0 = fmaf(w, p01.x, a0); a1 = fmaf(w, p01.y, a1);
        a2 = fmaf(w, p23.x, a2); a3 = fmaf(w, p23.y, a3);
    }
    const float bcv = bcp[0];
    *reinterpret_cast<float4*>(attn_out + ((size_t)b * SS + q) * SS + t * 4)
        = make_float4(a0 + bcv, a1 + bcv, a2 + bcv, a3 + bcv);
}

// ---------------- PV (single fp16 MMA; scale by invS; X out fp16 hi/lo) ----
#define PV_PTILE 10240            // 128*40*2
#define PV_VTILE 4608             // 32*72*2
#define PV_STAGE (PV_PTILE + PV_VTILE)   // 14848
#define PV_SMEM  (2*PV_STAGE)

__global__ __launch_bounds__(256) void pv_mma()
{
    extern __shared__ char smem[];
    const uint32_t sb = smem_to_u32(smem);
    const int tid = threadIdx.x, lane = tid & 31, wid = tid >> 5;
    const int wm = wid >> 1, wn = wid & 1;
    const int bh = blockIdx.y;
    const int m0 = blockIdx.x * 128;
    const int b = bh >> 4, h = bh & 15;

    auto issue = [&](int stage, int k0) {
        uint32_t s0 = sb + stage * PV_STAGE;
        #pragma unroll
        for (int i = 0; i < 3; i++) {
            int cid = i * 256 + tid;
            if (cid < 512) {
                int r = cid >> 2, c = cid & 3;
                const __half* g = g_Pf
                    + ((size_t)bh * 1024 + m0 + r) * 1024 + k0 + c * 8;
                cpa16(s0 + r * 80 + c * 16, g);
            } else {
                int idx = cid - 512;
                int r = idx >> 3, c = idx & 7;
                const __half* g = g_Vf
                    + ((size_t)bh * 1024 + k0 + r) * 64 + c * 8;
                cpa16(s0 + PV_PTILE + r * 144 + c * 16, g);
            }
        }
        CP_COMMIT();
    };

    float acc[2][4][4];
    #pragma unroll
    for (int i = 0; i < 2; i++)
        #pragma unroll
        for (int j = 0; j < 4; j++)
            #pragma unroll
            for (int c = 0; c < 4; c++) acc[i][j][c] = 0.f;

    issue(0, 0);
    for (int kc = 0; kc < 32; kc++) {
        if (kc < 31) { issue((kc + 1) & 1, (kc + 1) * 32); CP_WAIT(1); }
        else CP_WAIT(0);
        __syncthreads();
        const uint32_t s0 = sb + (kc & 1) * PV_STAGE;
        const uint32_t sP = s0, sV = s0 + PV_PTILE;

        #pragma unroll
        for (int ks = 0; ks < 2; ks++) {
            uint32_t a[2][4];
            #pragma unroll
            for (int i = 0; i < 2; i++) {
                uint32_t off = (uint32_t)(wm*32 + i*16 + (lane & 15)) * 80
                             + ((lane >> 4) * 16) + ks * 32;
                ldsm4(a[i], sP + off);
            }
            uint32_t b2[2][4];
            #pragma unroll
            for (int j2 = 0; j2 < 2; j2++) {
                uint32_t row = (uint32_t)(ks*16 + (lane & 7) + ((lane & 8) ? 8 : 0));
                uint32_t col = (uint32_t)(wn*32 + j2*16 + ((lane & 16) ? 8 : 0));
                ldsm4t(b2[j2], sV + row * 144 + col * 2);
            }
            #pragma unroll
            for (int i = 0; i < 2; i++)
                #pragma unroll
                for (int j = 0; j < 4; j++) {
                    int j2 = j >> 1, hh = (j & 1) * 2;
                    mma16816h(acc[i][j], a[i], b2[j2][hh], b2[j2][hh+1]);
                }
        }
        __syncthreads();
    }

    #pragma unroll
    for (int i = 0; i < 2; i++) {
        int qlo = m0 + wm*32 + i*16 + (lane >> 2);
        #pragma unroll
        for (int half = 0; half < 2; half++) {
            int q = qlo + half * 8;
            const float invS = g_invS[(size_t)bh * 1024 + q];
            #pragma unroll
            for (int j = 0; j < 4; j++) {
                int hd = wn*32 + j*8 + 2*(lane & 3);
                float v0 = acc[i][j][half*2 + 0] * invS;
                float v1 = acc[i][j][half*2 + 1] * invS;
                size_t o = ((size_t)(b * 1024 + q)) * 1024 + h * 64 + hd;
                ushort_t h0,l0,h1,l1;
                split1h(v0, h0, l0); split1h(v1, h1, l1);
                *reinterpret_cast<ushort2*>(g_Xhi + o) = make_ushort2(h0, h1);
                *reinterpret_cast<ushort2*>(g_Xlo + o) = make_ushort2(l0, l1);
            }
        }
    }
}

// ---------------------------------------------------------------------------
extern "C" void kernel_launch(void* const* d_in, const int* in_sizes, int n_in,
                              void* d_out, int out_size)
{
    (void)in_sizes; (void)n_in; (void)out_size;
    const float* query = (const float*)d_in[0];
    const float* key   = (const float*)d_in[1];
    const float* value = (const float*)d_in[2];
    const float* Wq = (const float*)d_in[3];  const float* bq = (const float*)d_in[4];
    const float* Wk = (const float*)d_in[5];  const float* bk = (const float*)d_in[6];
    const float* Wv = (const float*)d_in[7];  const float* bv = (const float*)d_in[8];
    const float* Wo = (const float*)d_in[9];  const float* bo = (const float*)d_in[10];
    const float* Wc = (const float*)d_in[11]; const float* bc = (const float*)d_in[12];

    float* out = (float*)d_out;
    float* attn_out = out + (size_t)BB * SS * DD;

    static bool attr_done = false;
    if (!attr_done) {
        cudaFuncSetAttribute(proj_qkv,   cudaFuncAttributeMaxDynamicSharedMemorySize, PJ_SMEM);
        cudaFuncSetAttribute(proj_out,   cudaFuncAttributeMaxDynamicSharedMemorySize, PJ_SMEM);
        cudaFuncSetAttribute(scores_exp, cudaFuncAttributeMaxDynamicSharedMemorySize, SC_SMEM);
        cudaFuncSetAttribute(pv_mma,     cudaFuncAttributeMaxDynamicSharedMemorySize, PV_SMEM);
        attr_done = true;
    }

    const int NACT4 = NACT / 4;

    split_act3<<<dim3(NACT4/256, 3), 256>>>(
        (const float4*)query, (const float4*)key, (const float4*)value);
    split_wT4<<<dim3(32, 32, 4), 256>>>(Wq, Wk, Wv, Wo);

    proj_qkv<<<dim3(8, 32, 3), 256, PJ_SMEM>>>(bq, bk, bv);

    // unnormalized exp scores -> Pf + partial sums
    scores_exp<<<dim3(8, 8, BB*HH), 256, SC_SMEM>>>();
    sumS<<<BB*HH*SS/256, 256>>>();

    attnc<<<BB * SS, 256>>>(Wc, bc, attn_out);
    pv_mma<<<dim3(8, BB*HH), 256, PV_SMEM>>>();

    proj_out<<<dim3(8, 32), 256, PJ_SMEM>>>(bo, out);
}

// round 12
// speedup vs baseline: 1.4895x; 1.4895x over previous
#include <cuda_runtime.h>
#include <cuda_bf16.h>
#include <cuda_fp16.h>
#include <math.h>
#include <stdint.h>

#define BB 4
#define SS 1024
#define DD 1024
#define HH 16
#define HD 64

typedef unsigned short ushort_t;

#define NACT (BB*SS*DD)           // 4M elements per activation plane

__device__ float    g_P [(size_t)BB*HH*SS*SS];    // fp32 scores (256MB)
__device__ __half   g_Pf[(size_t)BB*HH*SS*SS];    // probs fp16 (128MB)
__device__ __half   g_Qf[BB*HH*SS*HD];
__device__ __half   g_Kf[BB*HH*SS*HD];
__device__ __half   g_Vf[BB*HH*SS*HD];
__device__ ushort_t g_Xf [NACT];                  // X single fp16 plane
__device__ ushort_t g_Ahi[3*NACT], g_Alo[3*NACT]; // q/k/v activation fp16 hi/lo
__device__ ushort_t g_Bf [4*DD*DD];               // W^T fp16: q,k,v,o planes

// ---------------- helpers ----------------
__device__ __forceinline__ uint32_t smem_to_u32(const void* p) {
    uint32_t a;
    asm("{ .reg .u64 t; cvta.to.shared.u64 t, %1; cvt.u32.u64 %0, t; }"
        : "=r"(a) : "l"(p));
    return a;
}
__device__ __forceinline__ void cpa16(uint32_t s, const void* g) {
    asm volatile("cp.async.cg.shared.global [%0], [%1], 16;" :: "r"(s), "l"(g));
}
#define CP_COMMIT() asm volatile("cp.async.commit_group;")
#define CP_WAIT(n)  asm volatile("cp.async.wait_group %0;" :: "n"(n))

__device__ __forceinline__ void ldsm4(uint32_t* r, uint32_t addr) {
    asm volatile("ldmatrix.sync.aligned.m8n8.x4.shared.b16 {%0,%1,%2,%3}, [%4];"
        : "=r"(r[0]), "=r"(r[1]), "=r"(r[2]), "=r"(r[3]) : "r"(addr));
}
__device__ __forceinline__ void ldsm4t(uint32_t* r, uint32_t addr) {
    asm volatile("ldmatrix.sync.aligned.m8n8.x4.trans.shared.b16 {%0,%1,%2,%3}, [%4];"
        : "=r"(r[0]), "=r"(r[1]), "=r"(r[2]), "=r"(r[3]) : "r"(addr));
}
__device__ __forceinline__ void mma16816h(float* c, const uint32_t* a,
                                          uint32_t b0, uint32_t b1) {
    asm volatile(
        "mma.sync.aligned.m16n8k16.row.col.f32.f16.f16.f32 "
        "{%0,%1,%2,%3}, {%4,%5,%6,%7}, {%8,%9}, {%0,%1,%2,%3};"
        : "+f"(c[0]), "+f"(c[1]), "+f"(c[2]), "+f"(c[3])
        : "r"(a[0]), "r"(a[1]), "r"(a[2]), "r"(a[3]), "r"(b0), "r"(b1));
}
__device__ __forceinline__ void split1h(float v, ushort_t& h, ushort_t& l) {
    __half hb = __float2half_rn(v);
    float r = v - __half2float(hb);
    __half lb = __float2half_rn(r);
    h = __half_as_ushort(hb);
    l = __half_as_ushort(lb);
}

// ---------------- splits (merged launches) ----------------
__global__ __launch_bounds__(256) void split_act3(
    const float4* __restrict__ x0, const float4* __restrict__ x1,
    const float4* __restrict__ x2)
{
    const int z = blockIdx.y;
    const float4* x = (z == 0) ? x0 : (z == 1) ? x1 : x2;
    uint2* hi = reinterpret_cast<uint2*>(g_Ahi) + (size_t)z * (NACT/4);
    uint2* lo = reinterpret_cast<uint2*>(g_Alo) + (size_t)z * (NACT/4);
    int i = blockIdx.x * blockDim.x + threadIdx.x;
    float4 v = x[i];
    ushort_t h0,h1,h2,h3,l0,l1,l2,l3;
    split1h(v.x,h0,l0); split1h(v.y,h1,l1); split1h(v.z,h2,l2); split1h(v.w,h3,l3);
    hi[i] = make_uint2((uint32_t)h0 | ((uint32_t)h1 << 16),
                       (uint32_t)h2 | ((uint32_t)h3 << 16));
    if (z < 2)
        lo[i] = make_uint2((uint32_t)l0 | ((uint32_t)l1 << 16),
                           (uint32_t)l2 | ((uint32_t)l3 << 16));
}

__global__ __launch_bounds__(256) void split_wT4(
    const float* __restrict__ W0, const float* __restrict__ W1,
    const float* __restrict__ W2, const float* __restrict__ W3)
{
    const int z = blockIdx.z;
    const float* W = (z == 0) ? W0 : (z == 1) ? W1 : (z == 2) ? W2 : W3;
    ushort_t* bf = g_Bf + (size_t)z * DD * DD;
    __shared__ float t[32][33];
    int n0 = blockIdx.x * 32, k0 = blockIdx.y * 32;
    int tx = threadIdx.x & 31, ty = threadIdx.x >> 5;
    #pragma unroll
    for (int j = 0; j < 4; j++)
        t[ty + 8*j][tx] = W[(size_t)(k0 + ty + 8*j) * DD + n0 + tx];
    __syncthreads();
    #pragma unroll
    for (int j = 0; j < 4; j++) {
        float v = t[tx][ty + 8*j];
        bf[(size_t)(n0 + ty + 8*j) * DD + k0 + tx]
            = __half_as_ushort(__float2half_rn(v));
    }
}

// ---------------- projection GEMM ----------------
// DUAL=true : C = (Ahi+Alo)*B^T + bias   (2 MMAs)
// DUAL=false: C = A*B^T + bias           (1 MMA)
#define PJ_TILE   10240
#define PJ_STAGE3 (3*PJ_TILE)
#define PJ_SMEM3  (2*PJ_STAGE3)     // 61440
#define PJ_STAGE2 (2*PJ_TILE)
#define PJ_SMEM2  (2*PJ_STAGE2)     // 40960

template<bool DUAL>
__device__ __forceinline__ void proj_core(
    const ushort_t* __restrict__ Ahi, const ushort_t* __restrict__ Alo,
    const ushort_t* __restrict__ Bf, const float* __restrict__ bias,
    __half* __restrict__ Cf, float* __restrict__ Cext,
    char* smem, int m0, int n0)
{
    const uint32_t sb = smem_to_u32(smem);
    const int tid = threadIdx.x, lane = tid & 31, wid = tid >> 5;
    const int wm = wid >> 1, wn = wid & 1;
    const int STAGE = DUAL ? PJ_STAGE3 : PJ_STAGE2;

    auto issue = [&](int stage, int k0) {
        if (DUAL) {
            const ushort_t* gsrc[3] = {Ahi, Alo, Bf};
            #pragma unroll
            for (int i = 0; i < 6; i++) {
                int cid = i * 256 + tid;
                int t = cid >> 9;
                int idx = cid & 511;
                int r = idx >> 2, c = idx & 3;
                int grow = (t < 2 ? m0 : n0) + r;
                const ushort_t* g = gsrc[t] + (size_t)grow * 1024 + k0 + c * 8;
                cpa16(sb + stage * STAGE + t * PJ_TILE + r * 80 + c * 16, g);
            }
        } else {
            #pragma unroll
            for (int i = 0; i < 4; i++) {
                int cid = i * 256 + tid;
                int t = cid >> 9;               // 0 = A, 1 = B
                int idx = cid & 511;
                int r = idx >> 2, c = idx & 3;
                int grow = (t == 0 ? m0 : n0) + r;
                const ushort_t* g = (t == 0 ? Ahi : Bf)
                    + (size_t)grow * 1024 + k0 + c * 8;
                cpa16(sb + stage * STAGE + t * PJ_TILE + r * 80 + c * 16, g);
            }
        }
        CP_COMMIT();
    };

    float acc[2][8][4];
    #pragma unroll
    for (int i = 0; i < 2; i++)
        #pragma unroll
        for (int j = 0; j < 8; j++)
            #pragma unroll
            for (int c = 0; c < 4; c++) acc[i][j][c] = 0.f;

    issue(0, 0);
    for (int kc = 0; kc < 32; kc++) {
        if (kc < 31) { issue((kc + 1) & 1, (kc + 1) * 32); CP_WAIT(1); }
        else CP_WAIT(0);
        __syncthreads();
        const uint32_t s0  = sb + (kc & 1) * STAGE;
        const uint32_t sAh = s0;
        const uint32_t sAl = s0 + PJ_TILE;                       // dual only
        const uint32_t sB  = s0 + (DUAL ? 2 : 1) * PJ_TILE;

        #pragma unroll
        for (int ks = 0; ks < 2; ks++) {
            uint32_t ah[2][4], al[2][4];
            #pragma unroll
            for (int i = 0; i < 2; i++) {
                uint32_t off = (uint32_t)(wm*32 + i*16 + (lane & 15)) * 80
                             + ((lane >> 4) * 16) + ks * 32;
                ldsm4(ah[i], sAh + off);
                if (DUAL) ldsm4(al[i], sAl + off);
            }
            uint32_t b4[4][4];
            #pragma unroll
            for (int j4 = 0; j4 < 4; j4++) {
                uint32_t row = (uint32_t)(wn*64 + j4*16 + (lane & 7) + ((lane & 16) >> 1));
                uint32_t off = row * 80 + ks * 32 + ((lane & 8) << 1);
                ldsm4(b4[j4], sB + off);
            }
            #pragma unroll
            for (int i = 0; i < 2; i++)
                #pragma unroll
                for (int j = 0; j < 8; j++) {
                    int j4 = j >> 1, hh = (j & 1) * 2;
                    mma16816h(acc[i][j], ah[i], b4[j4][hh], b4[j4][hh+1]);
                    if (DUAL) mma16816h(acc[i][j], al[i], b4[j4][hh], b4[j4][hh+1]);
                }
        }
        __syncthreads();
    }

    #pragma unroll
    for (int i = 0; i < 2; i++) {
        int mlo = m0 + wm*32 + i*16 + (lane >> 2);
        #pragma unroll
        for (int half = 0; half < 2; half++) {
            int m = mlo + half * 8;
            int b = m >> 10, s = m & 1023;
            #pragma unroll
            for (int j = 0; j < 8; j++) {
                int col = n0 + wn*64 + j*8 + 2*(lane & 3);
                float v0 = acc[i][j][half*2 + 0] + bias[col];
                float v1 = acc[i][j][half*2 + 1] + bias[col + 1];
                if (Cext) {
                    *reinterpret_cast<float2*>(Cext + (size_t)m * 1024 + col)
                        = make_float2(v0, v1);
                } else {
                    int h = col >> 6, hd = col & 63;
                    size_t o = ((size_t)((b << 4) + h) * 1024 + s) * 64 + hd;
                    *reinterpret_cast<__half2*>(Cf + o) = __floats2half2_rn(v0, v1);
                }
            }
        }
    }
}

// Q,K projections (dual-A, exact split-2): grid (8, 32, 2)
__global__ __launch_bounds__(256) void proj_qk(
    const float* __restrict__ b0, const float* __restrict__ b1)
{
    extern __shared__ char smem[];
    const int z = blockIdx.z;
    proj_core<true>(g_Ahi + (size_t)z * NACT, g_Alo + (size_t)z * NACT,
                    g_Bf + (size_t)z * DD * DD,
                    (z == 0) ? b0 : b1,
                    (z == 0) ? g_Qf : g_Kf, nullptr, smem,
                    blockIdx.y * 128, blockIdx.x * 128);
}

// V projection (single-A fp16): grid (8, 32)
__global__ __launch_bounds__(256) void proj_v(const float* __restrict__ bias)
{
    extern __shared__ char smem[];
    proj_core<false>(g_Ahi + (size_t)2 * NACT, nullptr,
                     g_Bf + (size_t)2 * DD * DD, bias,
                     g_Vf, nullptr, smem,
                     blockIdx.y * 128, blockIdx.x * 128);
}

// out projection (single-A = g_Xf): grid (8, 32)
__global__ __launch_bounds__(256) void proj_out(
    const float* __restrict__ bias, float* __restrict__ Cext)
{
    extern __shared__ char smem[];
    proj_core<false>(g_Xf, nullptr, g_Bf + (size_t)3 * DD * DD, bias,
                     nullptr, Cext, smem,
                     blockIdx.y * 128, blockIdx.x * 128);
}

// ---------------- scores (single fp16 MMA) ----------------
#define SC_TILE  18432            // 128 rows * 72 elems * 2B
#define SC_SMEM  (2*SC_TILE)

__global__ __launch_bounds__(256) void scores_mma()
{
    extern __shared__ char smem[];
    const uint32_t sb = smem_to_u32(smem);
    const int tid = threadIdx.x, lane = tid & 31, wid = tid >> 5;
    const int wm = wid >> 1, wn = wid & 1;
    const int bh = blockIdx.z;
    const int m0 = blockIdx.y * 128, n0 = blockIdx.x * 128;

    #pragma unroll
    for (int i = 0; i < 8; i++) {
        int cid = i * 256 + tid;
        int t = cid >> 10;
        int idx = cid & 1023;
        int r = idx >> 3, c = idx & 7;
        int base = (t == 0 ? m0 : n0);
        const __half* g = (t == 0 ? g_Qf : g_Kf)
            + ((size_t)bh * 1024 + base + r) * 64 + c * 8;
        cpa16(sb + t * SC_TILE + r * 144 + c * 16, g);
    }
    CP_COMMIT();
    CP_WAIT(0);
    __syncthreads();

    const uint32_t sQ = sb, sK = sb + SC_TILE;

    float acc[2][8][4];
    #pragma unroll
    for (int i = 0; i < 2; i++)
        #pragma unroll
        for (int j = 0; j < 8; j++)
            #pragma unroll
            for (int c = 0; c < 4; c++) acc[i][j][c] = 0.f;

    #pragma unroll
    for (int ks = 0; ks < 4; ks++) {
        uint32_t a[2][4];
        #pragma unroll
        for (int i = 0; i < 2; i++) {
            uint32_t off = (uint32_t)(wm*32 + i*16 + (lane & 15)) * 144
                         + ((lane >> 4) * 16) + ks * 32;
            ldsm4(a[i], sQ + off);
        }
        uint32_t b4[4][4];
        #pragma unroll
        for (int j4 = 0; j4 < 4; j4++) {
            uint32_t row = (uint32_t)(wn*64 + j4*16 + (lane & 7) + ((lane & 16) >> 1));
            uint32_t off = row * 144 + ks * 32 + ((lane & 8) << 1);
            ldsm4(b4[j4], sK + off);
        }
        #pragma unroll
        for (int i = 0; i < 2; i++)
            #pragma unroll
            for (int j = 0; j < 8; j++) {
                int j4 = j >> 1, hh = (j & 1) * 2;
                mma16816h(acc[i][j], a[i], b4[j4][hh], b4[j4][hh+1]);
            }
    }

    float* Pp = g_P + (size_t)bh * SS * SS;
    #pragma unroll
    for (int i = 0; i < 2; i++) {
        int mlo = m0 + wm*32 + i*16 + (lane >> 2);
        #pragma unroll
        for (int half = 0; half < 2; half++) {
            int m = mlo + half * 8;
            #pragma unroll
            for (int j = 0; j < 8; j++) {
                int col = n0 + wn*64 + j*8 + 2*(lane & 3);
                *reinterpret_cast<float2*>(Pp + (size_t)m * SS + col)
                    = make_float2(acc[i][j][half*2+0] * 0.125f,
                                  acc[i][j][half*2+1] * 0.125f);
            }
        }
    }
}

// ---------------- softmax + attn_c (warp-per-row, round-8) ----------------
__global__ __launch_bounds__(256) void softmax_attnc(
    const float* __restrict__ Wc, const float* __restrict__ bcp,
    float* __restrict__ attn_out)
{
    const int b = blockIdx.x >> 10;
    const int q = blockIdx.x & 1023;
    const int tid = threadIdx.x;
    const int lane = tid & 31, w = tid >> 5;

    __shared__ float part[8][1024];

    float acc[8][4];
    #pragma unroll
    for (int i = 0; i < 8; i++)
        #pragma unroll
        for (int c = 0; c < 4; c++) acc[i][c] = 0.f;

    #pragma unroll
    for (int hi = 0; hi < 2; hi++) {
        const int h = w + hi * 8;
        size_t rowoff = ((size_t)((b << 4) + h) * SS + q) * SS;
        const float* row = g_P + rowoff;

        float4 v[8];
        #pragma unroll
        for (int i = 0; i < 8; i++)
            v[i] = *reinterpret_cast<const float4*>(row + i * 128 + lane * 4);

        float m = -1e30f;
        #pragma unroll
        for (int i = 0; i < 8; i++)
            m = fmaxf(m, fmaxf(fmaxf(v[i].x, v[i].y), fmaxf(v[i].z, v[i].w)));
        #pragma unroll
        for (int o = 16; o; o >>= 1) m = fmaxf(m, __shfl_xor_sync(0xffffffffu, m, o));

        float s = 0.f;
        #pragma unroll
        for (int i = 0; i < 8; i++) {
            v[i].x = expf(v[i].x - m); v[i].y = expf(v[i].y - m);
            v[i].z = expf(v[i].z - m); v[i].w = expf(v[i].w - m);
            s += v[i].x + v[i].y + v[i].z + v[i].w;
        }
        #pragma unroll
        for (int o = 16; o; o >>= 1) s += __shfl_xor_sync(0xffffffffu, s, o);
        const float inv = 1.f / s;
        const float wc = Wc[h];

        #pragma unroll
        for (int i = 0; i < 8; i++) {
            float p0 = v[i].x * inv, p1 = v[i].y * inv;
            float p2 = v[i].z * inv, p3 = v[i].w * inv;
            __half2 q0 = __floats2half2_rn(p0, p1);
            __half2 q1 = __floats2half2_rn(p2, p3);
            *reinterpret_cast<uint2*>(g_Pf + rowoff + i * 128 + lane * 4)
                = make_uint2(*reinterpret_cast<uint32_t*>(&q0),
                             *reinterpret_cast<uint32_t*>(&q1));
            acc[i][0] = fmaf(wc, p0, acc[i][0]);
            acc[i][1] = fmaf(wc, p1, acc[i][1]);
            acc[i][2] = fmaf(wc, p2, acc[i][2]);
            acc[i][3] = fmaf(wc, p3, acc[i][3]);
        }
    }

    #pragma unroll
    for (int i = 0; i < 8; i++)
        *reinterpret_cast<float4*>(&part[w][i * 128 + lane * 4])
            = make_float4(acc[i][0], acc[i][1], acc[i][2], acc[i][3]);
    __syncthreads();

    {
        const float bcv = bcp[0];
        float4 r = make_float4(bcv, bcv, bcv, bcv);
        #pragma unroll
        for (int ww = 0; ww < 8; ww++) {
            float4 p = *reinterpret_cast<float4*>(&part[ww][tid * 4]);
            r.x += p.x; r.y += p.y; r.z += p.z; r.w += p.w;
        }
        *reinterpret_cast<float4*>(
            attn_out + ((size_t)b * SS + q) * SS + tid * 4) = r;
    }
}

// ---------------- PV (single fp16 MMA; X out single fp16) ----------------
#define PV_PTILE 10240            // 128*40*2
#define PV_VTILE 4608             // 32*72*2
#define PV_STAGE (PV_PTILE + PV_VTILE)   // 14848
#define PV_SMEM  (2*PV_STAGE)

__global__ __launch_bounds__(256) void pv_mma()
{
    extern __shared__ char smem[];
    const uint32_t sb = smem_to_u32(smem);
    const int tid = threadIdx.x, lane = tid & 31, wid = tid >> 5;
    const int wm = wid >> 1, wn = wid & 1;
    const int bh = blockIdx.y;
    const int m0 = blockIdx.x * 128;
    const int b = bh >> 4, h = bh & 15;

    auto issue = [&](int stage, int k0) {
        uint32_t s0 = sb + stage * PV_STAGE;
        #pragma unroll
        for (int i = 0; i < 3; i++) {
            int cid = i * 256 + tid;
            if (cid < 512) {
                int r = cid >> 2, c = cid & 3;
                const __half* g = g_Pf
                    + ((size_t)bh * 1024 + m0 + r) * 1024 + k0 + c * 8;
                cpa16(s0 + r * 80 + c * 16, g);
            } else {
                int idx = cid - 512;
                int r = idx >> 3, c = idx & 7;
                const __half* g = g_Vf
                    + ((size_t)bh * 1024 + k0 + r) * 64 + c * 8;
                cpa16(s0 + PV_PTILE + r * 144 + c * 16, g);
            }
        }
        CP_COMMIT();
    };

    float acc[2][4][4];
    #pragma unroll
    for (int i = 0; i < 2; i++)
        #pragma unroll
        for (int j = 0; j < 4; j++)
            #pragma unroll
            for (int c = 0; c < 4; c++) acc[i][j][c] = 0.f;

    issue(0, 0);
    for (int kc = 0; kc < 32; kc++) {
        if (kc < 31) { issue((kc + 1) & 1, (kc + 1) * 32); CP_WAIT(1); }
        else CP_WAIT(0);
        __syncthreads();
        const uint32_t s0 = sb + (kc & 1) * PV_STAGE;
        const uint32_t sP = s0, sV = s0 + PV_PTILE;

        #pragma unroll
        for (int ks = 0; ks < 2; ks++) {
            uint32_t a[2][4];
            #pragma unroll
            for (int i = 0; i < 2; i++) {
                uint32_t off = (uint32_t)(wm*32 + i*16 + (lane & 15)) * 80
                             + ((lane >> 4) * 16) + ks * 32;
                ldsm4(a[i], sP + off);
            }
            uint32_t b2[2][4];
            #pragma unroll
            for (int j2 = 0; j2 < 2; j2++) {
                uint32_t row = (uint32_t)(ks*16 + (lane & 7) + ((lane & 8) ? 8 : 0));
                uint32_t col = (uint32_t)(wn*32 + j2*16 + ((lane & 16) ? 8 : 0));
                ldsm4t(b2[j2], sV + row * 144 + col * 2);
            }
            #pragma unroll
            for (int i = 0; i < 2; i++)
                #pragma unroll
                for (int j = 0; j < 4; j++) {
                    int j2 = j >> 1, hh = (j & 1) * 2;
                    mma16816h(acc[i][j], a[i], b2[j2][hh], b2[j2][hh+1]);
                }
        }
        __syncthreads();
    }

    #pragma unroll
    for (int i = 0; i < 2; i++) {
        int qlo = m0 + wm*32 + i*16 + (lane >> 2);
        #pragma unroll
        for (int half = 0; half < 2; half++) {
            int q = qlo + half * 8;
            #pragma unroll
            for (int j = 0; j < 4; j++) {
                int hd = wn*32 + j*8 + 2*(lane & 3);
                float v0 = acc[i][j][half*2 + 0];
                float v1 = acc[i][j][half*2 + 1];
                size_t o = ((size_t)(b * 1024 + q)) * 1024 + h * 64 + hd;
                *reinterpret_cast<__half2*>(g_Xf + o) = __floats2half2_rn(v0, v1);
            }
        }
    }
}

// ---------------------------------------------------------------------------
extern "C" void kernel_launch(void* const* d_in, const int* in_sizes, int n_in,
                              void* d_out, int out_size)
{
    (void)in_sizes; (void)n_in; (void)out_size;
    const float* query = (const float*)d_in[0];
    const float* key   = (const float*)d_in[1];
    const float* value = (const float*)d_in[2];
    const float* Wq = (const float*)d_in[3];  const float* bq = (const float*)d_in[4];
    const float* Wk = (const float*)d_in[5];  const float* bk = (const float*)d_in[6];
    const float* Wv = (const float*)d_in[7];  const float* bv = (const float*)d_in[8];
    const float* Wo = (const float*)d_in[9];  const float* bo = (const float*)d_in[10];
    const float* Wc = (const float*)d_in[11]; const float* bc = (const float*)d_in[12];

    float* out = (float*)d_out;
    float* attn_out = out + (size_t)BB * SS * DD;

    static bool attr_done = false;
    if (!attr_done) {
        cudaFuncSetAttribute(proj_qk,    cudaFuncAttributeMaxDynamicSharedMemorySize, PJ_SMEM3);
        cudaFuncSetAttribute(proj_v,     cudaFuncAttributeMaxDynamicSharedMemorySize, PJ_SMEM2);
        cudaFuncSetAttribute(proj_out,   cudaFuncAttributeMaxDynamicSharedMemorySize, PJ_SMEM2);
        cudaFuncSetAttribute(scores_mma, cudaFuncAttributeMaxDynamicSharedMemorySize, SC_SMEM);
        cudaFuncSetAttribute(pv_mma,     cudaFuncAttributeMaxDynamicSharedMemorySize, PV_SMEM);
        attr_done = true;
    }

    const int NACT4 = NACT / 4;

    split_act3<<<dim3(NACT4/256, 3), 256>>>(
        (const float4*)query, (const float4*)key, (const float4*)value);
    split_wT4<<<dim3(32, 32, 4), 256>>>(Wq, Wk, Wv, Wo);

    proj_qk<<<dim3(8, 32, 2), 256, PJ_SMEM3>>>(bq, bk);
    proj_v<<<dim3(8, 32), 256, PJ_SMEM2>>>(bv);

    scores_mma<<<dim3(8, 8, BB*HH), 256, SC_SMEM>>>();
    softmax_attnc<<<BB * SS, 256>>>(Wc, bc, attn_out);
    pv_mma<<<dim3(8, BB*HH), 256, PV_SMEM>>>();

    proj_out<<<dim3(8, 32), 256, PJ_SMEM2>>>(bo, out);
}

// round 13
// speedup vs baseline: 1.9256x; 1.2928x over previous
#include <cuda_runtime.h>
#include <cuda_bf16.h>
#include <cuda_fp16.h>
#include <math.h>
#include <stdint.h>

#define BB 4
#define SS 1024
#define DD 1024
#define HH 16
#define HD 64

typedef unsigned short ushort_t;

#define NACT (BB*SS*DD)           // 4M elements per activation plane

__device__ float    g_P [(size_t)BB*HH*SS*SS];    // fp32 scores (256MB)
__device__ __half   g_Pf[(size_t)BB*HH*SS*SS];    // probs fp16 (128MB)
__device__ __half   g_Qf[BB*HH*SS*HD];
__device__ __half   g_Kf[BB*HH*SS*HD];
__device__ __half   g_Vf[BB*HH*SS*HD];
__device__ ushort_t g_Xf [NACT];                  // X single fp16 plane
__device__ ushort_t g_Af [3*NACT];                // q/k/v activations fp16
__device__ ushort_t g_Bf [4*DD*DD];               // W^T fp16: q,k,v,o planes

// ---------------- helpers ----------------
__device__ __forceinline__ uint32_t smem_to_u32(const void* p) {
    uint32_t a;
    asm("{ .reg .u64 t; cvta.to.shared.u64 t, %1; cvt.u32.u64 %0, t; }"
        : "=r"(a) : "l"(p));
    return a;
}
__device__ __forceinline__ void cpa16(uint32_t s, const void* g) {
    asm volatile("cp.async.cg.shared.global [%0], [%1], 16;" :: "r"(s), "l"(g));
}
#define CP_COMMIT() asm volatile("cp.async.commit_group;")
#define CP_WAIT(n)  asm volatile("cp.async.wait_group %0;" :: "n"(n))

__device__ __forceinline__ void ldsm4(uint32_t* r, uint32_t addr) {
    asm volatile("ldmatrix.sync.aligned.m8n8.x4.shared.b16 {%0,%1,%2,%3}, [%4];"
        : "=r"(r[0]), "=r"(r[1]), "=r"(r[2]), "=r"(r[3]) : "r"(addr));
}
__device__ __forceinline__ void ldsm4t(uint32_t* r, uint32_t addr) {
    asm volatile("ldmatrix.sync.aligned.m8n8.x4.trans.shared.b16 {%0,%1,%2,%3}, [%4];"
        : "=r"(r[0]), "=r"(r[1]), "=r"(r[2]), "=r"(r[3]) : "r"(addr));
}
__device__ __forceinline__ void mma16816h(float* c, const uint32_t* a,
                                          uint32_t b0, uint32_t b1) {
    asm volatile(
        "mma.sync.aligned.m16n8k16.row.col.f32.f16.f16.f32 "
        "{%0,%1,%2,%3}, {%4,%5,%6,%7}, {%8,%9}, {%0,%1,%2,%3};"
        : "+f"(c[0]), "+f"(c[1]), "+f"(c[2]), "+f"(c[3])
        : "r"(a[0]), "r"(a[1]), "r"(a[2]), "r"(a[3]), "r"(b0), "r"(b1));
}

// ---------------- splits (merged launches) ----------------
__global__ __launch_bounds__(256) void split_act3(
    const float4* __restrict__ x0, const float4* __restrict__ x1,
    const float4* __restrict__ x2)
{
    const int z = blockIdx.y;
    const float4* x = (z == 0) ? x0 : (z == 1) ? x1 : x2;
    uint2* dst = reinterpret_cast<uint2*>(g_Af) + (size_t)z * (NACT/4);
    int i = blockIdx.x * blockDim.x + threadIdx.x;
    float4 v = x[i];
    __half2 a = __floats2half2_rn(v.x, v.y);
    __half2 b = __floats2half2_rn(v.z, v.w);
    dst[i] = make_uint2(*reinterpret_cast<uint32_t*>(&a),
                        *reinterpret_cast<uint32_t*>(&b));
}

__global__ __launch_bounds__(256) void split_wT4(
    const float* __restrict__ W0, const float* __restrict__ W1,
    const float* __restrict__ W2, const float* __restrict__ W3)
{
    const int z = blockIdx.z;
    const float* W = (z == 0) ? W0 : (z == 1) ? W1 : (z == 2) ? W2 : W3;
    ushort_t* bf = g_Bf + (size_t)z * DD * DD;
    __shared__ float t[32][33];
    int n0 = blockIdx.x * 32, k0 = blockIdx.y * 32;
    int tx = threadIdx.x & 31, ty = threadIdx.x >> 5;
    #pragma unroll
    for (int j = 0; j < 4; j++)
        t[ty + 8*j][tx] = W[(size_t)(k0 + ty + 8*j) * DD + n0 + tx];
    __syncthreads();
    #pragma unroll
    for (int j = 0; j < 4; j++) {
        float v = t[tx][ty + 8*j];
        bf[(size_t)(n0 + ty + 8*j) * DD + k0 + tx]
            = __half_as_ushort(__float2half_rn(v));
    }
}

// ---------------- projection GEMM (single-A fp16, 1 MMA) ----------------
#define PJ_TILE  10240
#define PJ_STAGE (2*PJ_TILE)
#define PJ_SMEM  (2*PJ_STAGE)     // 40960

__device__ __forceinline__ void proj_core(
    const ushort_t* __restrict__ Af, const ushort_t* __restrict__ Bf,
    const float* __restrict__ bias,
    __half* __restrict__ Cf, float* __restrict__ Cext,
    char* smem, int m0, int n0)
{
    const uint32_t sb = smem_to_u32(smem);
    const int tid = threadIdx.x, lane = tid & 31, wid = tid >> 5;
    const int wm = wid >> 1, wn = wid & 1;

    auto issue = [&](int stage, int k0) {
        #pragma unroll
        for (int i = 0; i < 4; i++) {
            int cid = i * 256 + tid;
            int t = cid >> 9;               // 0 = A, 1 = B
            int idx = cid & 511;
            int r = idx >> 2, c = idx & 3;
            int grow = (t == 0 ? m0 : n0) + r;
            const ushort_t* g = (t == 0 ? Af : Bf)
                + (size_t)grow * 1024 + k0 + c * 8;
            cpa16(sb + stage * PJ_STAGE + t * PJ_TILE + r * 80 + c * 16, g);
        }
        CP_COMMIT();
    };

    float acc[2][8][4];
    #pragma unroll
    for (int i = 0; i < 2; i++)
        #pragma unroll
        for (int j = 0; j < 8; j++)
            #pragma unroll
            for (int c = 0; c < 4; c++) acc[i][j][c] = 0.f;

    issue(0, 0);
    for (int kc = 0; kc < 32; kc++) {
        if (kc < 31) { issue((kc + 1) & 1, (kc + 1) * 32); CP_WAIT(1); }
        else CP_WAIT(0);
        __syncthreads();
        const uint32_t s0 = sb + (kc & 1) * PJ_STAGE;
        const uint32_t sA = s0, sB = s0 + PJ_TILE;

        #pragma unroll
        for (int ks = 0; ks < 2; ks++) {
            uint32_t a[2][4];
            #pragma unroll
            for (int i = 0; i < 2; i++) {
                uint32_t off = (uint32_t)(wm*32 + i*16 + (lane & 15)) * 80
                             + ((lane >> 4) * 16) + ks * 32;
                ldsm4(a[i], sA + off);
            }
            uint32_t b4[4][4];
            #pragma unroll
            for (int j4 = 0; j4 < 4; j4++) {
                uint32_t row = (uint32_t)(wn*64 + j4*16 + (lane & 7) + ((lane & 16) >> 1));
                uint32_t off = row * 80 + ks * 32 + ((lane & 8) << 1);
                ldsm4(b4[j4], sB + off);
            }
            #pragma unroll
            for (int i = 0; i < 2; i++)
                #pragma unroll
                for (int j = 0; j < 8; j++) {
                    int j4 = j >> 1, hh = (j & 1) * 2;
                    mma16816h(acc[i][j], a[i], b4[j4][hh], b4[j4][hh+1]);
                }
        }
        __syncthreads();
    }

    #pragma unroll
    for (int i = 0; i < 2; i++) {
        int mlo = m0 + wm*32 + i*16 + (lane >> 2);
        #pragma unroll
        for (int half = 0; half < 2; half++) {
            int m = mlo + half * 8;
            int b = m >> 10, s = m & 1023;
            #pragma unroll
            for (int j = 0; j < 8; j++) {
                int col = n0 + wn*64 + j*8 + 2*(lane & 3);
                float v0 = acc[i][j][half*2 + 0] + bias[col];
                float v1 = acc[i][j][half*2 + 1] + bias[col + 1];
                if (Cext) {
                    *reinterpret_cast<float2*>(Cext + (size_t)m * 1024 + col)
                        = make_float2(v0, v1);
                } else {
                    int h = col >> 6, hd = col & 63;
                    size_t o = ((size_t)((b << 4) + h) * 1024 + s) * 64 + hd;
                    *reinterpret_cast<__half2*>(Cf + o) = __floats2half2_rn(v0, v1);
                }
            }
        }
    }
}

// Q,K,V projections in one launch: grid (8, 32, 3)
__global__ __launch_bounds__(256) void proj_qkv(
    const float* __restrict__ b0, const float* __restrict__ b1,
    const float* __restrict__ b2)
{
    extern __shared__ char smem[];
    const int z = blockIdx.z;
    proj_core(g_Af + (size_t)z * NACT, g_Bf + (size_t)z * DD * DD,
              (z == 0) ? b0 : (z == 1) ? b1 : b2,
              (z == 0) ? g_Qf : (z == 1) ? g_Kf : g_Vf, nullptr, smem,
              blockIdx.y * 128, blockIdx.x * 128);
}

// out projection (A = g_Xf): grid (8, 32)
__global__ __launch_bounds__(256) void proj_out(
    const float* __restrict__ bias, float* __restrict__ Cext)
{
    extern __shared__ char smem[];
    proj_core(g_Xf, g_Bf + (size_t)3 * DD * DD, bias,
              nullptr, Cext, smem,
              blockIdx.y * 128, blockIdx.x * 128);
}

// ---------------- scores (single fp16 MMA) ----------------
#define SC_TILE  18432            // 128 rows * 72 elems * 2B
#define SC_SMEM  (2*SC_TILE)

__global__ __launch_bounds__(256) void scores_mma()
{
    extern __shared__ char smem[];
    const uint32_t sb = smem_to_u32(smem);
    const int tid = threadIdx.x, lane = tid & 31, wid = tid >> 5;
    const int wm = wid >> 1, wn = wid & 1;
    const int bh = blockIdx.z;
    const int m0 = blockIdx.y * 128, n0 = blockIdx.x * 128;

    #pragma unroll
    for (int i = 0; i < 8; i++) {
        int cid = i * 256 + tid;
        int t = cid >> 10;
        int idx = cid & 1023;
        int r = idx >> 3, c = idx & 7;
        int base = (t == 0 ? m0 : n0);
        const __half* g = (t == 0 ? g_Qf : g_Kf)
            + ((size_t)bh * 1024 + base + r) * 64 + c * 8;
        cpa16(sb + t * SC_TILE + r * 144 + c * 16, g);
    }
    CP_COMMIT();
    CP_WAIT(0);
    __syncthreads();

    const uint32_t sQ = sb, sK = sb + SC_TILE;

    float acc[2][8][4];
    #pragma unroll
    for (int i = 0; i < 2; i++)
        #pragma unroll
        for (int j = 0; j < 8; j++)
            #pragma unroll
            for (int c = 0; c < 4; c++) acc[i][j][c] = 0.f;

    #pragma unroll
    for (int ks = 0; ks < 4; ks++) {
        uint32_t a[2][4];
        #pragma unroll
        for (int i = 0; i < 2; i++) {
            uint32_t off = (uint32_t)(wm*32 + i*16 + (lane & 15)) * 144
                         + ((lane >> 4) * 16) + ks * 32;
            ldsm4(a[i], sQ + off);
        }
        uint32_t b4[4][4];
        #pragma unroll
        for (int j4 = 0; j4 < 4; j4++) {
            uint32_t row = (uint32_t)(wn*64 + j4*16 + (lane & 7) + ((lane & 16) >> 1));
            uint32_t off = row * 144 + ks * 32 + ((lane & 8) << 1);
            ldsm4(b4[j4], sK + off);
        }
        #pragma unroll
        for (int i = 0; i < 2; i++)
            #pragma unroll
            for (int j = 0; j < 8; j++) {
                int j4 = j >> 1, hh = (j & 1) * 2;
                mma16816h(acc[i][j], a[i], b4[j4][hh], b4[j4][hh+1]);
            }
    }

    float* Pp = g_P + (size_t)bh * SS * SS;
    #pragma unroll
    for (int i = 0; i < 2; i++) {
        int mlo = m0 + wm*32 + i*16 + (lane >> 2);
        #pragma unroll
        for (int half = 0; half < 2; half++) {
            int m = mlo + half * 8;
            #pragma unroll
            for (int j = 0; j < 8; j++) {
                int col = n0 + wn*64 + j*8 + 2*(lane & 3);
                *reinterpret_cast<float2*>(Pp + (size_t)m * SS + col)
                    = make_float2(acc[i][j][half*2+0] * 0.125f,
                                  acc[i][j][half*2+1] * 0.125f);
            }
        }
    }
}

// ---------------- softmax + attn_c (warp-per-row) ----------------
__global__ __launch_bounds__(256) void softmax_attnc(
    const float* __restrict__ Wc, const float* __restrict__ bcp,
    float* __restrict__ attn_out)
{
    const int b = blockIdx.x >> 10;
    const int q = blockIdx.x & 1023;
    const int tid = threadIdx.x;
    const int lane = tid & 31, w = tid >> 5;

    __shared__ float part[8][1024];

    float acc[8][4];
    #pragma unroll
    for (int i = 0; i < 8; i++)
        #pragma unroll
        for (int c = 0; c < 4; c++) acc[i][c] = 0.f;

    #pragma unroll
    for (int hi = 0; hi < 2; hi++) {
        const int h = w + hi * 8;
        size_t rowoff = ((size_t)((b << 4) + h) * SS + q) * SS;
        const float* row = g_P + rowoff;

        float4 v[8];
        #pragma unroll
        for (int i = 0; i < 8; i++)
            v[i] = *reinterpret_cast<const float4*>(row + i * 128 + lane * 4);

        float m = -1e30f;
        #pragma unroll
        for (int i = 0; i < 8; i++)
            m = fmaxf(m, fmaxf(fmaxf(v[i].x, v[i].y), fmaxf(v[i].z, v[i].w)));
        #pragma unroll
        for (int o = 16; o; o >>= 1) m = fmaxf(m, __shfl_xor_sync(0xffffffffu, m, o));

        float s = 0.f;
        #pragma unroll
        for (int i = 0; i < 8; i++) {
            v[i].x = expf(v[i].x - m); v[i].y = expf(v[i].y - m);
            v[i].z = expf(v[i].z - m); v[i].w = expf(v[i].w - m);
            s += v[i].x + v[i].y + v[i].z + v[i].w;
        }
        #pragma unroll
        for (int o = 16; o; o >>= 1) s += __shfl_xor_sync(0xffffffffu, s, o);
        const float inv = 1.f / s;
        const float wc = Wc[h];

        #pragma unroll
        for (int i = 0; i < 8; i++) {
            float p0 = v[i].x * inv, p1 = v[i].y * inv;
            float p2 = v[i].z * inv, p3 = v[i].w * inv;
            __half2 q0 = __floats2half2_rn(p0, p1);
            __half2 q1 = __floats2half2_rn(p2, p3);
            *reinterpret_cast<uint2*>(g_Pf + rowoff + i * 128 + lane * 4)
                = make_uint2(*reinterpret_cast<uint32_t*>(&q0),
                             *reinterpret_cast<uint32_t*>(&q1));
            acc[i][0] = fmaf(wc, p0, acc[i][0]);
            acc[i][1] = fmaf(wc, p1, acc[i][1]);
            acc[i][2] = fmaf(wc, p2, acc[i][2]);
            acc[i][3] = fmaf(wc, p3, acc[i][3]);
        }
    }

    #pragma unroll
    for (int i = 0; i < 8; i++)
        *reinterpret_cast<float4*>(&part[w][i * 128 + lane * 4])
            = make_float4(acc[i][0], acc[i][1], acc[i][2], acc[i][3]);
    __syncthreads();

    {
        const float bcv = bcp[0];
        float4 r = make_float4(bcv, bcv, bcv, bcv);
        #pragma unroll
        for (int ww = 0; ww < 8; ww++) {
            float4 p = *reinterpret_cast<float4*>(&part[ww][tid * 4]);
            r.x += p.x; r.y += p.y; r.z += p.z; r.w += p.w;
        }
        *reinterpret_cast<float4*>(
            attn_out + ((size_t)b * SS + q) * SS + tid * 4) = r;
    }
}

// ---------------- PV (single fp16 MMA; X out single fp16) ----------------
#define PV_PTILE 10240            // 128*40*2
#define PV_VTILE 4608             // 32*72*2
#define PV_STAGE (PV_PTILE + PV_VTILE)   // 14848
#define PV_SMEM  (2*PV_STAGE)

__global__ __launch_bounds__(256) void pv_mma()
{
    extern __shared__ char smem[];
    const uint32_t sb = smem_to_u32(smem);
    const int tid = threadIdx.x, lane = tid & 31, wid = tid >> 5;
    const int wm = wid >> 1, wn = wid & 1;
    const int bh = blockIdx.y;
    const int m0 = blockIdx.x * 128;
    const int b = bh >> 4, h = bh & 15;

    auto issue = [&](int stage, int k0) {
        uint32_t s0 = sb + stage * PV_STAGE;
        #pragma unroll
        for (int i = 0; i < 3; i++) {
            int cid = i * 256 + tid;
            if (cid < 512) {
                int r = cid >> 2, c = cid & 3;
                const __half* g = g_Pf
                    + ((size_t)bh * 1024 + m0 + r) * 1024 + k0 + c * 8;
                cpa16(s0 + r * 80 + c * 16, g);
            } else {
                int idx = cid - 512;
                int r = idx >> 3, c = idx & 7;
                const __half* g = g_Vf
                    + ((size_t)bh * 1024 + k0 + r) * 64 + c * 8;
                cpa16(s0 + PV_PTILE + r * 144 + c * 16, g);
            }
        }
        CP_COMMIT();
    };

    float acc[2][4][4];
    #pragma unroll
    for (int i = 0; i < 2; i++)
        #pragma unroll
        for (int j = 0; j < 4; j++)
            #pragma unroll
            for (int c = 0; c < 4; c++) acc[i][j][c] = 0.f;

    issue(0, 0);
    for (int kc = 0; kc < 32; kc++) {
        if (kc < 31) { issue((kc + 1) & 1, (kc + 1) * 32); CP_WAIT(1); }
        else CP_WAIT(0);
        __syncthreads();
        const uint32_t s0 = sb + (kc & 1) * PV_STAGE;
        const uint32_t sP = s0, sV = s0 + PV_PTILE;

        #pragma unroll
        for (int ks = 0; ks < 2; ks++) {
            uint32_t a[2][4];
            #pragma unroll
            for (int i = 0; i < 2; i++) {
                uint32_t off = (uint32_t)(wm*32 + i*16 + (lane & 15)) * 80
                             + ((lane >> 4) * 16) + ks * 32;
                ldsm4(a[i], sP + off);
            }
            uint32_t b2[2][4];
            #pragma unroll
            for (int j2 = 0; j2 < 2; j2++) {
                uint32_t row = (uint32_t)(ks*16 + (lane & 7) + ((lane & 8) ? 8 : 0));
                uint32_t col = (uint32_t)(wn*32 + j2*16 + ((lane & 16) ? 8 : 0));
                ldsm4t(b2[j2], sV + row * 144 + col * 2);
            }
            #pragma unroll
            for (int i = 0; i < 2; i++)
                #pragma unroll
                for (int j = 0; j < 4; j++) {
                    int j2 = j >> 1, hh = (j & 1) * 2;
                    mma16816h(acc[i][j], a[i], b2[j2][hh], b2[j2][hh+1]);
                }
        }
        __syncthreads();
    }

    #pragma unroll
    for (int i = 0; i < 2; i++) {
        int qlo = m0 + wm*32 + i*16 + (lane >> 2);
        #pragma unroll
        for (int half = 0; half < 2; half++) {
            int q = qlo + half * 8;
            #pragma unroll
            for (int j = 0; j < 4; j++) {
                int hd = wn*32 + j*8 + 2*(lane & 3);
                float v0 = acc[i][j][half*2 + 0];
                float v1 = acc[i][j][half*2 + 1];
                size_t o = ((size_t)(b * 1024 + q)) * 1024 + h * 64 + hd;
                *reinterpret_cast<__half2*>(g_Xf + o) = __floats2half2_rn(v0, v1);
            }
        }
    }
}

// ---------------------------------------------------------------------------
extern "C" void kernel_launch(void* const* d_in, const int* in_sizes, int n_in,
                              void* d_out, int out_size)
{
    (void)in_sizes; (void)n_in; (void)out_size;
    const float* query = (const float*)d_in[0];
    const float* key   = (const float*)d_in[1];
    const float* value = (const float*)d_in[2];
    const float* Wq = (const float*)d_in[3];  const float* bq = (const float*)d_in[4];
    const float* Wk = (const float*)d_in[5];  const float* bk = (const float*)d_in[6];
    const float* Wv = (const float*)d_in[7];  const float* bv = (const float*)d_in[8];
    const float* Wo = (const float*)d_in[9];  const float* bo = (const float*)d_in[10];
    const float* Wc = (const float*)d_in[11]; const float* bc = (const float*)d_in[12];

    float* out = (float*)d_out;
    float* attn_out = out + (size_t)BB * SS * DD;

    static bool attr_done = false;
    if (!attr_done) {
        cudaFuncSetAttribute(proj_qkv,   cudaFuncAttributeMaxDynamicSharedMemorySize, PJ_SMEM);
        cudaFuncSetAttribute(proj_out,   cudaFuncAttributeMaxDynamicSharedMemorySize, PJ_SMEM);
        cudaFuncSetAttribute(scores_mma, cudaFuncAttributeMaxDynamicSharedMemorySize, SC_SMEM);
        cudaFuncSetAttribute(pv_mma,     cudaFuncAttributeMaxDynamicSharedMemorySize, PV_SMEM);
        attr_done = true;
    }

    const int NACT4 = NACT / 4;

    split_act3<<<dim3(NACT4/256, 3), 256>>>(
        (const float4*)query, (const float4*)key, (const float4*)value);
    split_wT4<<<dim3(32, 32, 4), 256>>>(Wq, Wk, Wv, Wo);

    proj_qkv<<<dim3(8, 32, 3), 256, PJ_SMEM>>>(bq, bk, bv);

    scores_mma<<<dim3(8, 8, BB*HH), 256, SC_SMEM>>>();
    softmax_attnc<<<BB * SS, 256>>>(Wc, bc, attn_out);
    pv_mma<<<dim3(8, BB*HH), 256, PV_SMEM>>>();

    proj_out<<<dim3(8, 32), 256, PJ_SMEM>>>(bo, out);
}

// round 15
// speedup vs baseline: 2.0268x; 1.0526x over previous
#include <cuda_runtime.h>
#include <cuda_bf16.h>
#include <cuda_fp16.h>
#include <math.h>
#include <stdint.h>

#define BB 4
#define SS 1024
#define DD 1024
#define HH 16
#define HD 64

typedef unsigned short ushort_t;

#define NACT (BB*SS*DD)           // 4M elements per activation plane

__device__ __half   g_Pf[(size_t)BB*HH*SS*SS];    // fp16 scaled scores, then probs in-place (128MB)
__device__ __half   g_Qf[BB*HH*SS*HD];
__device__ __half   g_Kf[BB*HH*SS*HD];
__device__ __half   g_Vf[BB*HH*SS*HD];
__device__ ushort_t g_Xf [NACT];                  // X single fp16 plane
__device__ ushort_t g_Af [3*NACT];                // q/k/v activations fp16
__device__ ushort_t g_Bf [4*DD*DD];               // W^T fp16: q,k,v,o planes

// ---------------- helpers ----------------
__device__ __forceinline__ uint32_t smem_to_u32(const void* p) {
    uint32_t a;
    asm("{ .reg .u64 t; cvta.to.shared.u64 t, %1; cvt.u32.u64 %0, t; }"
        : "=r"(a) : "l"(p));
    return a;
}
__device__ __forceinline__ void cpa16(uint32_t s, const void* g) {
    asm volatile("cp.async.cg.shared.global [%0], [%1], 16;" :: "r"(s), "l"(g));
}
#define CP_COMMIT() asm volatile("cp.async.commit_group;")
#define CP_WAIT(n)  asm volatile("cp.async.wait_group %0;" :: "n"(n))

__device__ __forceinline__ void ldsm4(uint32_t* r, uint32_t addr) {
    asm volatile("ldmatrix.sync.aligned.m8n8.x4.shared.b16 {%0,%1,%2,%3}, [%4];"
        : "=r"(r[0]), "=r"(r[1]), "=r"(r[2]), "=r"(r[3]) : "r"(addr));
}
__device__ __forceinline__ void ldsm4t(uint32_t* r, uint32_t addr) {
    asm volatile("ldmatrix.sync.aligned.m8n8.x4.trans.shared.b16 {%0,%1,%2,%3}, [%4];"
        : "=r"(r[0]), "=r"(r[1]), "=r"(r[2]), "=r"(r[3]) : "r"(addr));
}
__device__ __forceinline__ void mma16816h(float* c, const uint32_t* a,
                                          uint32_t b0, uint32_t b1) {
    asm volatile(
        "mma.sync.aligned.m16n8k16.row.col.f32.f16.f16.f32 "
        "{%0,%1,%2,%3}, {%4,%5,%6,%7}, {%8,%9}, {%0,%1,%2,%3};"
        : "+f"(c[0]), "+f"(c[1]), "+f"(c[2]), "+f"(c[3])
        : "r"(a[0]), "r"(a[1]), "r"(a[2]), "r"(a[3]), "r"(b0), "r"(b1));
}

// ---------------- splits (merged launches) ----------------
__global__ __launch_bounds__(256) void split_act3(
    const float4* __restrict__ x0, const float4* __restrict__ x1,
    const float4* __restrict__ x2)
{
    const int z = blockIdx.y;
    const float4* x = (z == 0) ? x0 : (z == 1) ? x1 : x2;
    uint2* dst = reinterpret_cast<uint2*>(g_Af) + (size_t)z * (NACT/4);
    int i = blockIdx.x * blockDim.x + threadIdx.x;
    float4 v = x[i];
    __half2 a = __floats2half2_rn(v.x, v.y);
    __half2 b = __floats2half2_rn(v.z, v.w);
    dst[i] = make_uint2(*reinterpret_cast<uint32_t*>(&a),
                        *reinterpret_cast<uint32_t*>(&b));
}

__global__ __launch_bounds__(256) void split_wT4(
    const float* __restrict__ W0, const float* __restrict__ W1,
    const float* __restrict__ W2, const float* __restrict__ W3)
{
    const int z = blockIdx.z;
    const float* W = (z == 0) ? W0 : (z == 1) ? W1 : (z == 2) ? W2 : W3;
    ushort_t* bf = g_Bf + (size_t)z * DD * DD;
    __shared__ float t[32][33];
    int n0 = blockIdx.x * 32, k0 = blockIdx.y * 32;
    int tx = threadIdx.x & 31, ty = threadIdx.x >> 5;
    #pragma unroll
    for (int j = 0; j < 4; j++)
        t[ty + 8*j][tx] = W[(size_t)(k0 + ty + 8*j) * DD + n0 + tx];
    __syncthreads();
    #pragma unroll
    for (int j = 0; j < 4; j++) {
        float v = t[tx][ty + 8*j];
        bf[(size_t)(n0 + ty + 8*j) * DD + k0 + tx]
            = __half_as_ushort(__float2half_rn(v));
    }
}

// ---------------- projection GEMM (single-A fp16, 1 MMA) ----------------
#define PJ_TILE  10240
#define PJ_STAGE (2*PJ_TILE)
#define PJ_SMEM  (2*PJ_STAGE)     // 40960

__device__ __forceinline__ void proj_core(
    const ushort_t* __restrict__ Af, const ushort_t* __restrict__ Bf,
    const float* __restrict__ bias,
    __half* __restrict__ Cf, float* __restrict__ Cext,
    char* smem, int m0, int n0)
{
    const uint32_t sb = smem_to_u32(smem);
    const int tid = threadIdx.x, lane = tid & 31, wid = tid >> 5;
    const int wm = wid >> 1, wn = wid & 1;

    auto issue = [&](int stage, int k0) {
        #pragma unroll
        for (int i = 0; i < 4; i++) {
            int cid = i * 256 + tid;
            int t = cid >> 9;               // 0 = A, 1 = B
            int idx = cid & 511;
            int r = idx >> 2, c = idx & 3;
            int grow = (t == 0 ? m0 : n0) + r;
            const ushort_t* g = (t == 0 ? Af : Bf)
                + (size_t)grow * 1024 + k0 + c * 8;
            cpa16(sb + stage * PJ_STAGE + t * PJ_TILE + r * 80 + c * 16, g);
        }
        CP_COMMIT();
    };

    float acc[2][8][4];
    #pragma unroll
    for (int i = 0; i < 2; i++)
        #pragma unroll
        for (int j = 0; j < 8; j++)
            #pragma unroll
            for (int c = 0; c < 4; c++) acc[i][j][c] = 0.f;

    issue(0, 0);
    for (int kc = 0; kc < 32; kc++) {
        if (kc < 31) { issue((kc + 1) & 1, (kc + 1) * 32); CP_WAIT(1); }
        else CP_WAIT(0);
        __syncthreads();
        const uint32_t s0 = sb + (kc & 1) * PJ_STAGE;
        const uint32_t sA = s0, sB = s0 + PJ_TILE;

        #pragma unroll
        for (int ks = 0; ks < 2; ks++) {
            uint32_t a[2][4];
            #pragma unroll
            for (int i = 0; i < 2; i++) {
                uint32_t off = (uint32_t)(wm*32 + i*16 + (lane & 15)) * 80
                             + ((lane >> 4) * 16) + ks * 32;
                ldsm4(a[i], sA + off);
            }
            uint32_t b4[4][4];
            #pragma unroll
            for (int j4 = 0; j4 < 4; j4++) {
                uint32_t row = (uint32_t)(wn*64 + j4*16 + (lane & 7) + ((lane & 16) >> 1));
                uint32_t off = row * 80 + ks * 32 + ((lane & 8) << 1);
                ldsm4(b4[j4], sB + off);
            }
            #pragma unroll
            for (int i = 0; i < 2; i++)
                #pragma unroll
                for (int j = 0; j < 8; j++) {
                    int j4 = j >> 1, hh = (j & 1) * 2;
                    mma16816h(acc[i][j], a[i], b4[j4][hh], b4[j4][hh+1]);
                }
        }
        __syncthreads();
    }

    #pragma unroll
    for (int i = 0; i < 2; i++) {
        int mlo = m0 + wm*32 + i*16 + (lane >> 2);
        #pragma unroll
        for (int half = 0; half < 2; half++) {
            int m = mlo + half * 8;
            int b = m >> 10, s = m & 1023;
            #pragma unroll
            for (int j = 0; j < 8; j++) {
                int col = n0 + wn*64 + j*8 + 2*(lane & 3);
                float v0 = acc[i][j][half*2 + 0] + bias[col];
                float v1 = acc[i][j][half*2 + 1] + bias[col + 1];
                if (Cext) {
                    *reinterpret_cast<float2*>(Cext + (size_t)m * 1024 + col)
                        = make_float2(v0, v1);
                } else {
                    int h = col >> 6, hd = col & 63;
                    size_t o = ((size_t)((b << 4) + h) * 1024 + s) * 64 + hd;
                    *reinterpret_cast<__half2*>(Cf + o) = __floats2half2_rn(v0, v1);
                }
            }
        }
    }
}

// Q,K,V projections in one launch: grid (8, 32, 3)
__global__ __launch_bounds__(256) void proj_qkv(
    const float* __restrict__ b0, const float* __restrict__ b1,
    const float* __restrict__ b2)
{
    extern __shared__ char smem[];
    const int z = blockIdx.z;
    proj_core(g_Af + (size_t)z * NACT, g_Bf + (size_t)z * DD * DD,
              (z == 0) ? b0 : (z == 1) ? b1 : b2,
              (z == 0) ? g_Qf : (z == 1) ? g_Kf : g_Vf, nullptr, smem,
              blockIdx.y * 128, blockIdx.x * 128);
}

// out projection (A = g_Xf): grid (8, 32)
__global__ __launch_bounds__(256) void proj_out(
    const float* __restrict__ bias, float* __restrict__ Cext)
{
    extern __shared__ char smem[];
    proj_core(g_Xf, g_Bf + (size_t)3 * DD * DD, bias,
              nullptr, Cext, smem,
              blockIdx.y * 128, blockIdx.x * 128);
}

// ---------------- scores (single fp16 MMA; fp16 scaled-score output) -------
#define SC_TILE  18432            // 128 rows * 72 elems * 2B
#define SC_SMEM  (2*SC_TILE)

__global__ __launch_bounds__(256) void scores_mma()
{
    extern __shared__ char smem[];
    const uint32_t sb = smem_to_u32(smem);
    const int tid = threadIdx.x, lane = tid & 31, wid = tid >> 5;
    const int wm = wid >> 1, wn = wid & 1;
    const int bh = blockIdx.z;
    const int m0 = blockIdx.y * 128, n0 = blockIdx.x * 128;

    #pragma unroll
    for (int i = 0; i < 8; i++) {
        int cid = i * 256 + tid;
        int t = cid >> 10;
        int idx = cid & 1023;
        int r = idx >> 3, c = idx & 7;
        int base = (t == 0 ? m0 : n0);
        const __half* g = (t == 0 ? g_Qf : g_Kf)
            + ((size_t)bh * 1024 + base + r) * 64 + c * 8;
        cpa16(sb + t * SC_TILE + r * 144 + c * 16, g);
    }
    CP_COMMIT();
    CP_WAIT(0);
    __syncthreads();

    const uint32_t sQ = sb, sK = sb + SC_TILE;

    float acc[2][8][4];
    #pragma unroll
    for (int i = 0; i < 2; i++)
        #pragma unroll
        for (int j = 0; j < 8; j++)
            #pragma unroll
            for (int c = 0; c < 4; c++) acc[i][j][c] = 0.f;

    #pragma unroll
    for (int ks = 0; ks < 4; ks++) {
        uint32_t a[2][4];
        #pragma unroll
        for (int i = 0; i < 2; i++) {
            uint32_t off = (uint32_t)(wm*32 + i*16 + (lane & 15)) * 144
                         + ((lane >> 4) * 16) + ks * 32;
            ldsm4(a[i], sQ + off);
        }
        uint32_t b4[4][4];
        #pragma unroll
        for (int j4 = 0; j4 < 4; j4++) {
            uint32_t row = (uint32_t)(wn*64 + j4*16 + (lane & 7) + ((lane & 16) >> 1));
            uint32_t off = row * 144 + ks * 32 + ((lane & 8) << 1);
            ldsm4(b4[j4], sK + off);
        }
        #pragma unroll
        for (int i = 0; i < 2; i++)
            #pragma unroll
            for (int j = 0; j < 8; j++) {
                int j4 = j >> 1, hh = (j & 1) * 2;
                mma16816h(acc[i][j], a[i], b4[j4][hh], b4[j4][hh+1]);
            }
    }

    __half* Pp = g_Pf + (size_t)bh * SS * SS;
    #pragma unroll
    for (int i = 0; i < 2; i++) {
        int mlo = m0 + wm*32 + i*16 + (lane >> 2);
        #pragma unroll
        for (int half = 0; half < 2; half++) {
            int m = mlo + half * 8;
            #pragma unroll
            for (int j = 0; j < 8; j++) {
                int col = n0 + wn*64 + j*8 + 2*(lane & 3);
                *reinterpret_cast<__half2*>(Pp + (size_t)m * SS + col)
                    = __floats2half2_rn(acc[i][j][half*2+0] * 0.125f,
                                        acc[i][j][half*2+1] * 0.125f);
            }
        }
    }
}

// ---------------- softmax + attn_c (warp-per-row, in-place on g_Pf) --------
__global__ __launch_bounds__(256) void softmax_attnc(
    const float* __restrict__ Wc, const float* __restrict__ bcp,
    float* __restrict__ attn_out)
{
    const int b = blockIdx.x >> 10;
    const int q = blockIdx.x & 1023;
    const int tid = threadIdx.x;
    const int lane = tid & 31, w = tid >> 5;

    __shared__ float part[8][1024];

    float acc[8][4];
    #pragma unroll
    for (int i = 0; i < 8; i++)
        #pragma unroll
        for (int c = 0; c < 4; c++) acc[i][c] = 0.f;

    #pragma unroll
    for (int hi = 0; hi < 2; hi++) {
        const int h = w + hi * 8;
        size_t rowoff = ((size_t)((b << 4) + h) * SS + q) * SS;
        __half* row = g_Pf + rowoff;

        float4 v[8];
        #pragma unroll
        for (int i = 0; i < 8; i++) {
            uint2 raw = *reinterpret_cast<const uint2*>(row + i * 128 + lane * 4);
            float2 p01 = __half22float2(*reinterpret_cast<const __half2*>(&raw.x));
            float2 p23 = __half22float2(*reinterpret_cast<const __half2*>(&raw.y));
            v[i] = make_float4(p01.x, p01.y, p23.x, p23.y);
        }

        float m = -1e30f;
        #pragma unroll
        for (int i = 0; i < 8; i++)
            m = fmaxf(m, fmaxf(fmaxf(v[i].x, v[i].y), fmaxf(v[i].z, v[i].w)));
        #pragma unroll
        for (int o = 16; o; o >>= 1) m = fmaxf(m, __shfl_xor_sync(0xffffffffu, m, o));

        float s = 0.f;
        #pragma unroll
        for (int i = 0; i < 8; i++) {
            v[i].x = expf(v[i].x - m); v[i].y = expf(v[i].y - m);
            v[i].z = expf(v[i].z - m); v[i].w = expf(v[i].w - m);
            s += v[i].x + v[i].y + v[i].z + v[i].w;
        }
        #pragma unroll
        for (int o = 16; o; o >>= 1) s += __shfl_xor_sync(0xffffffffu, s, o);
        const float inv = 1.f / s;
        const float wc = Wc[h];

        #pragma unroll
        for (int i = 0; i < 8; i++) {
            float p0 = v[i].x * inv, p1 = v[i].y * inv;
            float p2 = v[i].z * inv, p3 = v[i].w * inv;
            __half2 q0 = __floats2half2_rn(p0, p1);
            __half2 q1 = __floats2half2_rn(p2, p3);
            *reinterpret_cast<uint2*>(row + i * 128 + lane * 4)
                = make_uint2(*reinterpret_cast<uint32_t*>(&q0),
                             *reinterpret_cast<uint32_t*>(&q1));
            acc[i][0] = fmaf(wc, p0, acc[i][0]);
            acc[i][1] = fmaf(wc, p1, acc[i][1]);
            acc[i][2] = fmaf(wc, p2, acc[i][2]);
            acc[i][3] = fmaf(wc, p3, acc[i][3]);
        }
    }

    #pragma unroll
    for (int i = 0; i < 8; i++)
        *reinterpret_cast<float4*>(&part[w][i * 128 + lane * 4])
            = make_float4(acc[i][0], acc[i][1], acc[i][2], acc[i][3]);
    __syncthreads();

    {
        const float bcv = bcp[0];
        float4 r = make_float4(bcv, bcv, bcv, bcv);
        #pragma unroll
        for (int ww = 0; ww < 8; ww++) {
            float4 p = *reinterpret_cast<float4*>(&part[ww][tid * 4]);
            r.x += p.x; r.y += p.y; r.z += p.z; r.w += p.w;
        }
        *reinterpret_cast<float4*>(
            attn_out + ((size_t)b * SS + q) * SS + tid * 4) = r;
    }
}

// ---------------- PV (single fp16 MMA; X out single fp16) ----------------
#define PV_PTILE 10240            // 128*40*2
#define PV_VTILE 4608             // 32*72*2
#define PV_STAGE (PV_PTILE + PV_VTILE)   // 14848
#define PV_SMEM  (2*PV_STAGE)

__global__ __launch_bounds__(256) void pv_mma()
{
    extern __shared__ char smem[];
    const uint32_t sb = smem_to_u32(smem);
    const int tid = threadIdx.x, lane = tid & 31, wid = tid >> 5;
    const int wm = wid >> 1, wn = wid & 1;
    const int bh = blockIdx.y;
    const int m0 = blockIdx.x * 128;
    const int b = bh >> 4, h = bh & 15;

    auto issue = [&](int stage, int k0) {
        uint32_t s0 = sb + stage * PV_STAGE;
        #pragma unroll
        for (int i = 0; i < 3; i++) {
            int cid = i * 256 + tid;
            if (cid < 512) {
                int r = cid >> 2, c = cid & 3;
                const __half* g = g_Pf
                    + ((size_t)bh * 1024 + m0 + r) * 1024 + k0 + c * 8;
                cpa16(s0 + r * 80 + c * 16, g);
            } else {
                int idx = cid - 512;
                int r = idx >> 3, c = idx & 7;
                const __half* g = g_Vf
                    + ((size_t)bh * 1024 + k0 + r) * 64 + c * 8;
                cpa16(s0 + PV_PTILE + r * 144 + c * 16, g);
            }
        }
        CP_COMMIT();
    };

    float acc[2][4][4];
    #pragma unroll
    for (int i = 0; i < 2; i++)
        #pragma unroll
        for (int j = 0; j < 4; j++)
            #pragma unroll
            for (int c = 0; c < 4; c++) acc[i][j][c] = 0.f;

    issue(0, 0);
    for (int kc = 0; kc < 32; kc++) {
        if (kc < 31) { issue((kc + 1) & 1, (kc + 1) * 32); CP_WAIT(1); }
        else CP_WAIT(0);
        __syncthreads();
        const uint32_t s0 = sb + (kc & 1) * PV_STAGE;
        const uint32_t sP = s0, sV = s0 + PV_PTILE;

        #pragma unroll
        for (int ks = 0; ks < 2; ks++) {
            uint32_t a[2][4];
            #pragma unroll
            for (int i = 0; i < 2; i++) {
                uint32_t off = (uint32_t)(wm*32 + i*16 + (lane & 15)) * 80
                             + ((lane >> 4) * 16) + ks * 32;
                ldsm4(a[i], sP + off);
            }
            uint32_t b2[2][4];
            #pragma unroll
            for (int j2 = 0; j2 < 2; j2++) {
                uint32_t row = (uint32_t)(ks*16 + (lane & 7) + ((lane & 8) ? 8 : 0));
                uint32_t col = (uint32_t)(wn*32 + j2*16 + ((lane & 16) ? 8 : 0));
                ldsm4t(b2[j2], sV + row * 144 + col * 2);
            }
            #pragma unroll
            for (int i = 0; i < 2; i++)
                #pragma unroll
                for (int j = 0; j < 4; j++) {
                    int j2 = j >> 1, hh = (j & 1) * 2;
                    mma16816h(acc[i][j], a[i], b2[j2][hh], b2[j2][hh+1]);
                }
        }
        __syncthreads();
    }

    #pragma unroll
    for (int i = 0; i < 2; i++) {
        int qlo = m0 + wm*32 + i*16 + (lane >> 2);
        #pragma unroll
        for (int half = 0; half < 2; half++) {
            int q = qlo + half * 8;
            #pragma unroll
            for (int j = 0; j < 4; j++) {
                int hd = wn*32 + j*8 + 2*(lane & 3);
                float v0 = acc[i][j][half*2 + 0];
                float v1 = acc[i][j][half*2 + 1];
                size_t o = ((size_t)(b * 1024 + q)) * 1024 + h * 64 + hd;
                *reinterpret_cast<__half2*>(g_Xf + o) = __floats2half2_rn(v0, v1);
            }
        }
    }
}

// ---------------------------------------------------------------------------
extern "C" void kernel_launch(void* const* d_in, const int* in_sizes, int n_in,
                              void* d_out, int out_size)
{
    (void)in_sizes; (void)n_in; (void)out_size;
    const float* query = (const float*)d_in[0];
    const float* key   = (const float*)d_in[1];
    const float* value = (const float*)d_in[2];
    const float* Wq = (const float*)d_in[3];  const float* bq = (const float*)d_in[4];
    const float* Wk = (const float*)d_in[5];  const float* bk = (const float*)d_in[6];
    const float* Wv = (const float*)d_in[7];  const float* bv = (const float*)d_in[8];
    const float* Wo = (const float*)d_in[9];  const float* bo = (const float*)d_in[10];
    const float* Wc = (const float*)d_in[11]; const float* bc = (const float*)d_in[12];

    float* out = (float*)d_out;
    float* attn_out = out + (size_t)BB * SS * DD;

    static bool attr_done = false;
    if (!attr_done) {
        cudaFuncSetAttribute(proj_qkv,   cudaFuncAttributeMaxDynamicSharedMemorySize, PJ_SMEM);
        cudaFuncSetAttribute(proj_out,   cudaFuncAttributeMaxDynamicSharedMemorySize, PJ_SMEM);
        cudaFuncSetAttribute(scores_mma, cudaFuncAttributeMaxDynamicSharedMemorySize, SC_SMEM);
        cudaFuncSetAttribute(pv_mma,     cudaFuncAttributeMaxDynamicSharedMemorySize, PV_SMEM);
        attr_done = true;
    }

    const int NACT4 = NACT / 4;

    split_act3<<<dim3(NACT4/256, 3), 256>>>(
        (const float4*)query, (const float4*)key, (const float4*)value);
    split_wT4<<<dim3(32, 32, 4), 256>>>(Wq, Wk, Wv, Wo);

    proj_qkv<<<dim3(8, 32, 3), 256, PJ_SMEM>>>(bq, bk, bv);

    scores_mma<<<dim3(8, 8, BB*HH), 256, SC_SMEM>>>();
    softmax_attnc<<<BB * SS, 256>>>(Wc, bc, attn_out);
    pv_mma<<<dim3(8, BB*HH), 256, PV_SMEM>>>();

    proj_out<<<dim3(8, 32), 256, PJ_SMEM>>>(bo, out);
}